// round 4
// baseline (speedup 1.0000x reference)
#include <cuda_runtime.h>

#define NB 4
#define NC 128
#define NN 8192
#define NKN 16

typedef unsigned long long u64;

// Scratch (static device allocations — allowed)
__device__ __align__(16) float g_Y[(size_t)NB * NN * 256];  // [b][n][c] c<128: local, c>=128: edge
__device__ float g_sums[640];   // [0:128) sumL [128:256) sumL2 [256:384) sumE [384:512) sumE2 [512:640) cross

__device__ __forceinline__ u64 ff2(u64 a, u64 b, u64 c) {
    u64 d;
    asm("fma.rn.f32x2 %0, %1, %2, %3;" : "=l"(d) : "l"(a), "l"(b), "l"(c));
    return d;
}
__device__ __forceinline__ u64 pk2(float x) {
    u64 r;
    asm("mov.b64 %0, {%1, %1};" : "=l"(r) : "f"(x));
    return r;
}
__device__ __forceinline__ float lo32(u64 v) { return __uint_as_float((unsigned)v); }
__device__ __forceinline__ float hi32(u64 v) { return __uint_as_float((unsigned)(v >> 32)); }

// ---------------------------------------------------------------------------
// K1: Y[b][n][half*128+o] = sum_c W[o][c] * feat[b][c][n]
// Block tile: O=128 (full half) x N=128. Thread tile: 8 O x 8 n (4 n-pairs),
// 32 FFMA2 accumulator chains. Double-buffered smem, 1 sync per K-chunk.
// ---------------------------------------------------------------------------
__global__ void __launch_bounds__(256, 2) gemm_kernel(
    const float* __restrict__ feat, const float* __restrict__ W1,
    const float* __restrict__ W2)
{
    __shared__ float Wsm[2][16 * 132];  // [buf][kk][o], padded stride 132
    __shared__ float Fs[2][16 * 128];   // [buf][kk][n]

    const int tid  = threadIdx.x;
    const int b    = blockIdx.z;
    const int half = blockIdx.y;
    const int n0   = blockIdx.x * 128;

    if (blockIdx.x == 0 && blockIdx.y == 0 && blockIdx.z == 0) {
        for (int i = tid; i < 640; i += 256) g_sums[i] = 0.0f;
    }

    const float* __restrict__ Wg = half ? W2 : W1;

    const int ocol = tid & 15;      // o-block: o0 = ocol*8
    const int nrow = tid >> 4;      // n-block: nb = nrow*8
    const int o0   = ocol * 8;
    const int nb   = nrow * 8;
    const int r    = tid >> 4;      // staging row 0..15
    const int cg   = tid & 15;      // staging col group (8 floats)

    u64 acc2[8][4];
#pragma unroll
    for (int i = 0; i < 8; i++)
#pragma unroll
        for (int j = 0; j < 4; j++) acc2[i][j] = 0ULL;

    const float* fbase = &feat[(size_t)b * NC * NN + n0];

    // prologue: load chunk 0 into buf 0
    {
        float4 fa = *(const float4*)&fbase[(size_t)r * NN + cg * 8];
        float4 fb = *(const float4*)&fbase[(size_t)r * NN + cg * 8 + 4];
        *(float4*)&Fs[0][r * 128 + cg * 8]     = fa;
        *(float4*)&Fs[0][r * 128 + cg * 8 + 4] = fb;
#pragma unroll
        for (int it = 0; it < 8; it++) {
            int idx = it * 256 + tid;
            int o = idx >> 4, kk = idx & 15;
            Wsm[0][kk * 132 + o] = Wg[o * 128 + kk];
        }
    }
    __syncthreads();

    for (int kc = 0; kc < 8; kc++) {
        const int cur = kc & 1;
        // prefetch next chunk into registers
        float4 pfa, pfb;
        float pw[8];
        if (kc < 7) {
            const int k0 = (kc + 1) * 16;
            pfa = *(const float4*)&fbase[(size_t)(k0 + r) * NN + cg * 8];
            pfb = *(const float4*)&fbase[(size_t)(k0 + r) * NN + cg * 8 + 4];
#pragma unroll
            for (int it = 0; it < 8; it++) {
                int idx = it * 256 + tid;
                int o = idx >> 4, kk = idx & 15;
                pw[it] = Wg[o * 128 + k0 + kk];
            }
        }

        // compute on current buffer
#pragma unroll
        for (int kk = 0; kk < 16; kk++) {
            float4 wa = *(const float4*)&Wsm[cur][kk * 132 + o0];
            float4 wb = *(const float4*)&Wsm[cur][kk * 132 + o0 + 4];
            ulonglong2 f01 = *(const ulonglong2*)&Fs[cur][kk * 128 + nb];
            ulonglong2 f23 = *(const ulonglong2*)&Fs[cur][kk * 128 + nb + 4];
            u64 f2[4] = {f01.x, f01.y, f23.x, f23.y};
            u64 wp[8] = {pk2(wa.x), pk2(wa.y), pk2(wa.z), pk2(wa.w),
                         pk2(wb.x), pk2(wb.y), pk2(wb.z), pk2(wb.w)};
#pragma unroll
            for (int i = 0; i < 8; i++)
#pragma unroll
                for (int j = 0; j < 4; j++)
                    acc2[i][j] = ff2(wp[i], f2[j], acc2[i][j]);
        }

        // store prefetched chunk into the other buffer
        if (kc < 7) {
            const int nxt = cur ^ 1;
            *(float4*)&Fs[nxt][r * 128 + cg * 8]     = pfa;
            *(float4*)&Fs[nxt][r * 128 + cg * 8 + 4] = pfb;
#pragma unroll
            for (int it = 0; it < 8; it++) {
                int idx = it * 256 + tid;
                int o = idx >> 4, kk = idx & 15;
                Wsm[nxt][kk * 132 + o] = pw[it];
            }
            __syncthreads();
        }
    }

    // epilogue: write Y[b][n][half*128 + o0..o0+7] for n = nb..nb+7
#pragma unroll
    for (int j = 0; j < 4; j++) {
        size_t row = ((size_t)(b * NN + n0 + nb + 2 * j)) * 256 + half * 128 + o0;
        float4 v0a = make_float4(lo32(acc2[0][j]), lo32(acc2[1][j]),
                                 lo32(acc2[2][j]), lo32(acc2[3][j]));
        float4 v0b = make_float4(lo32(acc2[4][j]), lo32(acc2[5][j]),
                                 lo32(acc2[6][j]), lo32(acc2[7][j]));
        float4 v1a = make_float4(hi32(acc2[0][j]), hi32(acc2[1][j]),
                                 hi32(acc2[2][j]), hi32(acc2[3][j]));
        float4 v1b = make_float4(hi32(acc2[4][j]), hi32(acc2[5][j]),
                                 hi32(acc2[6][j]), hi32(acc2[7][j]));
        *(float4*)&g_Y[row]           = v0a;
        *(float4*)&g_Y[row + 4]       = v0b;
        *(float4*)&g_Y[row + 256]     = v1a;
        *(float4*)&g_Y[row + 256 + 4] = v1b;
    }
}

// ---------------------------------------------------------------------------
// K2: per-channel partial sums via gather. Grid-stride over bn for perfect
// wave balance (grid 592 = 4 CTAs/SM). Warp per bn, lane owns 4 channels.
// ---------------------------------------------------------------------------
__global__ void __launch_bounds__(256) stats_kernel(const int* __restrict__ knn)
{
    __shared__ float s[640];
    const int tid = threadIdx.x;
    for (int i = tid; i < 640; i += 256) s[i] = 0.0f;
    __syncthreads();

    const int lane = tid & 31, wrp = tid >> 5;
    const int c4 = lane * 4;
    const int stride = gridDim.x * 8;

    float4 aL  = {0,0,0,0}, aL2 = {0,0,0,0}, aE = {0,0,0,0};
    float4 aE2 = {0,0,0,0}, aX  = {0,0,0,0};

    for (int bn = blockIdx.x * 8 + wrp; bn < NB * NN; bn += stride) {
        int my_idx = 0;
        if (lane < 16) my_idx = knn[bn * NKN + lane];
        const float4 l = *(const float4*)&g_Y[(size_t)bn * 256 + c4];
        const int boff = bn & ~(NN - 1);   // b*NN
        float4 S = {0,0,0,0}, Q = {0,0,0,0};
#pragma unroll
        for (int k = 0; k < 16; k++) {
            const int m = __shfl_sync(0xffffffffu, my_idx, k);
            const float4 e = *(const float4*)&g_Y[((size_t)(boff + m)) * 256 + 128 + c4];
            S.x += e.x; S.y += e.y; S.z += e.z; S.w += e.w;
            Q.x = fmaf(e.x, e.x, Q.x); Q.y = fmaf(e.y, e.y, Q.y);
            Q.z = fmaf(e.z, e.z, Q.z); Q.w = fmaf(e.w, e.w, Q.w);
        }
        aE.x += S.x; aE.y += S.y; aE.z += S.z; aE.w += S.w;
        aE2.x += Q.x; aE2.y += Q.y; aE2.z += Q.z; aE2.w += Q.w;
        aX.x = fmaf(S.x, l.x, aX.x); aX.y = fmaf(S.y, l.y, aX.y);
        aX.z = fmaf(S.z, l.z, aX.z); aX.w = fmaf(S.w, l.w, aX.w);
        aL.x += l.x; aL.y += l.y; aL.z += l.z; aL.w += l.w;
        aL2.x = fmaf(l.x, l.x, aL2.x); aL2.y = fmaf(l.y, l.y, aL2.y);
        aL2.z = fmaf(l.z, l.z, aL2.z); aL2.w = fmaf(l.w, l.w, aL2.w);
    }

    atomicAdd(&s[c4 + 0], aL.x);  atomicAdd(&s[c4 + 1], aL.y);
    atomicAdd(&s[c4 + 2], aL.z);  atomicAdd(&s[c4 + 3], aL.w);
    atomicAdd(&s[128 + c4 + 0], aL2.x); atomicAdd(&s[128 + c4 + 1], aL2.y);
    atomicAdd(&s[128 + c4 + 2], aL2.z); atomicAdd(&s[128 + c4 + 3], aL2.w);
    atomicAdd(&s[256 + c4 + 0], aE.x);  atomicAdd(&s[256 + c4 + 1], aE.y);
    atomicAdd(&s[256 + c4 + 2], aE.z);  atomicAdd(&s[256 + c4 + 3], aE.w);
    atomicAdd(&s[384 + c4 + 0], aE2.x); atomicAdd(&s[384 + c4 + 1], aE2.y);
    atomicAdd(&s[384 + c4 + 2], aE2.z); atomicAdd(&s[384 + c4 + 3], aE2.w);
    atomicAdd(&s[512 + c4 + 0], aX.x);  atomicAdd(&s[512 + c4 + 1], aX.y);
    atomicAdd(&s[512 + c4 + 2], aX.z);  atomicAdd(&s[512 + c4 + 3], aX.w);
    __syncthreads();
    for (int i = tid; i < 640; i += 256) atomicAdd(&g_sums[i], s[i]);
}

// ---------------------------------------------------------------------------
// K3: output. Finalize (stats -> per-channel a,b) replicated per block into
// smem, then re-gather + ReLU + mean-over-k; smem tile -> coalesced writes.
// ---------------------------------------------------------------------------
__global__ void __launch_bounds__(256) output_kernel(const int* __restrict__ knn,
                                                     const float* __restrict__ gamma,
                                                     const float* __restrict__ beta,
                                                     float* __restrict__ out)
{
    __shared__ float tile[32 * 257];
    __shared__ float sa[256], sb[256];
    const int tid = threadIdx.x, lane = tid & 31, wrp = tid >> 5;
    const int c4 = lane * 4;
    const int bn0 = blockIdx.x * 32;  // grid 1024

    // replicated finalize: per-channel affine from global stats
    {
        const int c = tid;  // 0..255
        const float invBN  = 1.0f / (float)(NB * NN);
        const float invBNK = 1.0f / (float)((size_t)NB * NN * NKN);
        float mean, var;
        if (c < 128) {
            float sL = g_sums[c], sL2 = g_sums[128 + c];
            mean = sL * invBN;
            var  = sL2 * invBN - mean * mean;
        } else {
            int cc = c - 128;
            float sL  = g_sums[cc],       sL2 = g_sums[128 + cc];
            float sE  = g_sums[256 + cc], sE2 = g_sums[384 + cc];
            float sX  = g_sums[512 + cc];
            float sD  = sE - (float)NKN * sL;
            float sD2 = sE2 - 2.0f * sX + (float)NKN * sL2;
            mean = sD * invBNK;
            var  = sD2 * invBNK - mean * mean;
        }
        float a = gamma[c] * rsqrtf(var + 1e-5f);
        sa[c] = a;
        sb[c] = beta[c] - mean * a;
    }
    __syncthreads();

    const float4 a1 = *(const float4*)&sa[c4];
    const float4 b1 = *(const float4*)&sb[c4];
    const float4 a2 = *(const float4*)&sa[128 + c4];
    const float4 b2 = *(const float4*)&sb[128 + c4];

    for (int t = 0; t < 4; t++) {
        const int col = wrp * 4 + t;
        const int bn = bn0 + col;
        int my_idx = 0;
        if (lane < 16) my_idx = knn[bn * NKN + lane];
        const float4 l = *(const float4*)&g_Y[(size_t)bn * 256 + c4];
        const int boff = bn & ~(NN - 1);
        float4 S = {0,0,0,0};
#pragma unroll
        for (int k = 0; k < 16; k++) {
            const int m = __shfl_sync(0xffffffffu, my_idx, k);
            const float4 e = *(const float4*)&g_Y[((size_t)(boff + m)) * 256 + 128 + c4];
            S.x += fmaxf(fmaf(a2.x, e.x - l.x, b2.x), 0.0f);
            S.y += fmaxf(fmaf(a2.y, e.y - l.y, b2.y), 0.0f);
            S.z += fmaxf(fmaf(a2.z, e.z - l.z, b2.z), 0.0f);
            S.w += fmaxf(fmaf(a2.w, e.w - l.w, b2.w), 0.0f);
        }
        tile[col * 257 + c4 + 0] = fmaxf(fmaf(a1.x, l.x, b1.x), 0.0f);
        tile[col * 257 + c4 + 1] = fmaxf(fmaf(a1.y, l.y, b1.y), 0.0f);
        tile[col * 257 + c4 + 2] = fmaxf(fmaf(a1.z, l.z, b1.z), 0.0f);
        tile[col * 257 + c4 + 3] = fmaxf(fmaf(a1.w, l.w, b1.w), 0.0f);
        const float inv = 1.0f / 16.0f;
        tile[col * 257 + 128 + c4 + 0] = S.x * inv;
        tile[col * 257 + 128 + c4 + 1] = S.y * inv;
        tile[col * 257 + 128 + c4 + 2] = S.z * inv;
        tile[col * 257 + 128 + c4 + 3] = S.w * inv;
    }
    __syncthreads();

    const int b = bn0 >> 13;          // NN = 8192
    const int n0 = bn0 & (NN - 1);
#pragma unroll 4
    for (int i = 0; i < 32; i++) {
        int j = i * 256 + tid;
        int row = j >> 5, col = j & 31;
        out[((size_t)(b * 256 + row)) * NN + n0 + col] = tile[col * 257 + row];
    }
}

extern "C" void kernel_launch(void* const* d_in, const int* in_sizes, int n_in,
                              void* d_out, int out_size)
{
    const float* feat  = (const float*)d_in[0];
    const int*   knn   = (const int*)d_in[1];
    const float* W1    = (const float*)d_in[2];
    const float* W2    = (const float*)d_in[3];
    const float* gamma = (const float*)d_in[4];
    const float* beta  = (const float*)d_in[5];
    float* out = (float*)d_out;

    gemm_kernel<<<dim3(NN / 128, 2, NB), 256>>>(feat, W1, W2);
    stats_kernel<<<592, 256>>>(knn);
    output_kernel<<<1024, 256>>>(knn, gamma, beta, out);
}

// round 7
// speedup vs baseline: 1.0707x; 1.0707x over previous
#include <cuda_runtime.h>
#include <cuda_bf16.h>
#include <cstdint>

#define NB 4
#define NC 128
#define NN 8192
#define NKN 16

// ------------------------- scratch (static device) -------------------------
__device__ __align__(16) float g_Y[(size_t)NB * NN * 256];  // [bn][c] c<128 local, c>=128 edge
__device__ float g_sums[640];

// ------------------------- helpers -------------------------
__device__ __forceinline__ uint32_t smem_u32(const void* p) {
    uint32_t a;
    asm("{ .reg .u64 t; cvta.to.shared.u64 t, %1; cvt.u32.u64 %0, t; }" : "=r"(a) : "l"(p));
    return a;
}
__device__ __forceinline__ void ldmx4(uint32_t r[4], uint32_t addr) {
    asm volatile("ldmatrix.sync.aligned.m8n8.x4.shared.b16 {%0,%1,%2,%3}, [%4];"
                 : "=r"(r[0]), "=r"(r[1]), "=r"(r[2]), "=r"(r[3]) : "r"(addr));
}
__device__ __forceinline__ void mma_bf16(float c[4], const uint32_t a[4],
                                         uint32_t b0, uint32_t b1) {
    asm volatile(
        "mma.sync.aligned.m16n8k16.row.col.f32.bf16.bf16.f32 "
        "{%0,%1,%2,%3}, {%4,%5,%6,%7}, {%8,%9}, {%0,%1,%2,%3};"
        : "+f"(c[0]), "+f"(c[1]), "+f"(c[2]), "+f"(c[3])
        : "r"(a[0]), "r"(a[1]), "r"(a[2]), "r"(a[3]), "r"(b0), "r"(b1));
}

// smem layout (halves), padded stride 136 (272B rows -> 16B-aligned ldmatrix)
#define LDAH 136
#define OFF_AHI 0
#define OFF_ALO (128 * LDAH)
#define OFF_BHI (2 * 128 * LDAH)
#define OFF_BLO (2 * 128 * LDAH + 256 * LDAH)
#define SMEM_HALVES (2 * 128 * LDAH + 2 * 256 * LDAH)
#define SMEM_BYTES (SMEM_HALVES * 2)      // 208896

// ---------------------------------------------------------------------------
// K1: fused convert + HMMA GEMM.
// Grid 256 CTAs (one 128-n tile, all 256 o), 512 threads (16 warps).
// Y[bn][o] = sum_c feat[b][c][n] * W[o][c]  (W = W1 stacked over W2)
// fp32 -> bf16 hi/lo split, 3 passes: Ahi*Bhi + Ahi*Blo + Alo*Bhi.
// ---------------------------------------------------------------------------
__global__ void __launch_bounds__(512, 1) mma_gemm_kernel(
    const float* __restrict__ feat, const float* __restrict__ W1,
    const float* __restrict__ W2)
{
    extern __shared__ __align__(16) char smem[];
    __nv_bfloat16* sm = (__nv_bfloat16*)smem;

    const int tid = threadIdx.x;
    const int bn0 = blockIdx.x * 128;
    const int b   = blockIdx.x >> 6;           // NN/128 = 64 tiles per batch
    const int n0  = (blockIdx.x & 63) * 128;

    if (blockIdx.x == 0) {
        for (int i = tid; i < 640; i += 512) g_sums[i] = 0.0f;
    }

    // ---- fill B: 256 o-rows x 32 quads (c4) ----
#pragma unroll
    for (int it = 0; it < 16; it++) {
        int flat = it * 512 + tid;             // 0..8191
        int o = flat >> 5, c = (flat & 31) * 4;
        float4 w = (o < 128) ? *(const float4*)&W1[o * 128 + c]
                             : *(const float4*)&W2[(o - 128) * 128 + c];
        float x[4] = {w.x, w.y, w.z, w.w};
        __nv_bfloat16 h[4], l[4];
#pragma unroll
        for (int j = 0; j < 4; j++) {
            h[j] = __float2bfloat16(x[j]);
            l[j] = __float2bfloat16(x[j] - __bfloat162float(h[j]));
        }
        *(uint2*)&sm[OFF_BHI + o * LDAH + c] = *(uint2*)h;
        *(uint2*)&sm[OFF_BLO + o * LDAH + c] = *(uint2*)l;
    }

    // ---- fill A: transpose feat[b][c][n0..] -> sm[n][c], convert ----
#pragma unroll
    for (int it = 0; it < 8; it++) {
        int flat = it * 512 + tid;             // 0..4095 : 128c x 32 n-quads
        int c = flat >> 5, n = (flat & 31) * 4;
        float4 v = *(const float4*)&feat[((size_t)b * NC + c) * NN + n0 + n];
        float x[4] = {v.x, v.y, v.z, v.w};
#pragma unroll
        for (int j = 0; j < 4; j++) {
            __nv_bfloat16 h = __float2bfloat16(x[j]);
            __nv_bfloat16 l = __float2bfloat16(x[j] - __bfloat162float(h));
            sm[OFF_AHI + (n + j) * LDAH + c] = h;
            sm[OFF_ALO + (n + j) * LDAH + c] = l;
        }
    }
    __syncthreads();

    // ---- warp tiling: 16 warps = 4 n-blocks x 4 o-blocks; warp 32n x 64o ----
    const int wid = tid >> 5, lane = tid & 31;
    const int nb = (wid & 3) * 32;
    const int ob = (wid >> 2) * 64;

    float acc[2][8][4];
#pragma unroll
    for (int i = 0; i < 2; i++)
#pragma unroll
        for (int j = 0; j < 8; j++)
#pragma unroll
            for (int r = 0; r < 4; r++) acc[i][j][r] = 0.0f;

    // ldmatrix lane address pattern (same for A and B, K-contiguous)
    const int lrow  = (lane & 7) + ((lane >> 3) & 1) * 8;
    const int lkoff = (lane >> 4) * 8;         // halves
    const uint32_t smb = smem_u32(smem);
    const uint32_t aAddr = smb + (uint32_t)(((nb + lrow) * LDAH + lkoff) * 2);
    const uint32_t bAddr = smb + (uint32_t)(((ob + lrow) * LDAH + lkoff) * 2);

    const uint32_t aPass[3] = {OFF_AHI * 2, OFF_AHI * 2, OFF_ALO * 2};
    const uint32_t bPass[3] = {OFF_BHI * 2, OFF_BLO * 2, OFF_BHI * 2};

#pragma unroll
    for (int p = 0; p < 3; p++) {
        const uint32_t aB = aAddr + aPass[p];
        const uint32_t bB = bAddr + bPass[p];
#pragma unroll
        for (int ks = 0; ks < 8; ks++) {
            const uint32_t ko = ks * 32;       // 16 halves = 32 bytes
            uint32_t afr[2][4];
            ldmx4(afr[0], aB + ko);
            ldmx4(afr[1], aB + 16 * LDAH * 2 + ko);
            uint32_t bfr[4][4];
#pragma unroll
            for (int bt = 0; bt < 4; bt++)
                ldmx4(bfr[bt], bB + bt * 16 * LDAH * 2 + ko);
#pragma unroll
            for (int af = 0; af < 2; af++)
#pragma unroll
                for (int bt = 0; bt < 4; bt++) {
                    mma_bf16(acc[af][bt * 2 + 0], afr[af], bfr[bt][0], bfr[bt][2]);
                    mma_bf16(acc[af][bt * 2 + 1], afr[af], bfr[bt][1], bfr[bt][3]);
                }
        }
    }

    // ---- epilogue: direct float2 stores to g_Y ----
#pragma unroll
    for (int af = 0; af < 2; af++) {
#pragma unroll
        for (int ot = 0; ot < 8; ot++) {
            int row = bn0 + nb + af * 16 + (lane >> 2);
            int col = ob + ot * 8 + (lane & 3) * 2;
            *(float2*)&g_Y[(size_t)row * 256 + col] =
                make_float2(acc[af][ot][0], acc[af][ot][1]);
            *(float2*)&g_Y[(size_t)(row + 8) * 256 + col] =
                make_float2(acc[af][ot][2], acc[af][ot][3]);
        }
    }
}

// ---------------------------------------------------------------------------
// K2: stats gather (unchanged, proven)
// ---------------------------------------------------------------------------
__global__ void __launch_bounds__(256) stats_kernel(const int* __restrict__ knn)
{
    __shared__ float s[640];
    const int tid = threadIdx.x;
    for (int i = tid; i < 640; i += 256) s[i] = 0.0f;
    __syncthreads();

    const int lane = tid & 31, wrp = tid >> 5;
    const int c4 = lane * 4;
    const int stride = gridDim.x * 8;

    float4 aL = {0,0,0,0}, aL2 = {0,0,0,0}, aE = {0,0,0,0};
    float4 aE2 = {0,0,0,0}, aX = {0,0,0,0};

    for (int bn = blockIdx.x * 8 + wrp; bn < NB * NN; bn += stride) {
        int my_idx = 0;
        if (lane < 16) my_idx = knn[bn * NKN + lane];
        const float4 l = *(const float4*)&g_Y[(size_t)bn * 256 + c4];
        const int boff = bn & ~(NN - 1);
        float4 S = {0,0,0,0}, Q = {0,0,0,0};
#pragma unroll
        for (int k = 0; k < 16; k++) {
            const int m = __shfl_sync(0xffffffffu, my_idx, k);
            const float4 e = *(const float4*)&g_Y[((size_t)(boff + m)) * 256 + 128 + c4];
            S.x += e.x; S.y += e.y; S.z += e.z; S.w += e.w;
            Q.x = fmaf(e.x, e.x, Q.x); Q.y = fmaf(e.y, e.y, Q.y);
            Q.z = fmaf(e.z, e.z, Q.z); Q.w = fmaf(e.w, e.w, Q.w);
        }
        aE.x += S.x; aE.y += S.y; aE.z += S.z; aE.w += S.w;
        aE2.x += Q.x; aE2.y += Q.y; aE2.z += Q.z; aE2.w += Q.w;
        aX.x = fmaf(S.x, l.x, aX.x); aX.y = fmaf(S.y, l.y, aX.y);
        aX.z = fmaf(S.z, l.z, aX.z); aX.w = fmaf(S.w, l.w, aX.w);
        aL.x += l.x; aL.y += l.y; aL.z += l.z; aL.w += l.w;
        aL2.x = fmaf(l.x, l.x, aL2.x); aL2.y = fmaf(l.y, l.y, aL2.y);
        aL2.z = fmaf(l.z, l.z, aL2.z); aL2.w = fmaf(l.w, l.w, aL2.w);
    }

    atomicAdd(&s[c4 + 0], aL.x);  atomicAdd(&s[c4 + 1], aL.y);
    atomicAdd(&s[c4 + 2], aL.z);  atomicAdd(&s[c4 + 3], aL.w);
    atomicAdd(&s[128 + c4 + 0], aL2.x); atomicAdd(&s[128 + c4 + 1], aL2.y);
    atomicAdd(&s[128 + c4 + 2], aL2.z); atomicAdd(&s[128 + c4 + 3], aL2.w);
    atomicAdd(&s[256 + c4 + 0], aE.x);  atomicAdd(&s[256 + c4 + 1], aE.y);
    atomicAdd(&s[256 + c4 + 2], aE.z);  atomicAdd(&s[256 + c4 + 3], aE.w);
    atomicAdd(&s[384 + c4 + 0], aE2.x); atomicAdd(&s[384 + c4 + 1], aE2.y);
    atomicAdd(&s[384 + c4 + 2], aE2.z); atomicAdd(&s[384 + c4 + 3], aE2.w);
    atomicAdd(&s[512 + c4 + 0], aX.x);  atomicAdd(&s[512 + c4 + 1], aX.y);
    atomicAdd(&s[512 + c4 + 2], aX.z);  atomicAdd(&s[512 + c4 + 3], aX.w);
    __syncthreads();
    for (int i = tid; i < 640; i += 256) atomicAdd(&g_sums[i], s[i]);
}

// ---------------------------------------------------------------------------
// K3: output gather (unchanged, proven)
// ---------------------------------------------------------------------------
__global__ void __launch_bounds__(256) output_kernel(const int* __restrict__ knn,
                                                     const float* __restrict__ gamma,
                                                     const float* __restrict__ beta,
                                                     float* __restrict__ out)
{
    __shared__ float tile[32 * 257];
    __shared__ float sa[256], sb[256];
    const int tid = threadIdx.x, lane = tid & 31, wrp = tid >> 5;
    const int c4 = lane * 4;
    const int bn0 = blockIdx.x * 32;

    {
        const int c = tid;
        const float invBN  = 1.0f / (float)(NB * NN);
        const float invBNK = 1.0f / (float)((size_t)NB * NN * NKN);
        float mean, var;
        if (c < 128) {
            float sL = g_sums[c], sL2 = g_sums[128 + c];
            mean = sL * invBN;
            var  = sL2 * invBN - mean * mean;
        } else {
            int cc = c - 128;
            float sL  = g_sums[cc],       sL2 = g_sums[128 + cc];
            float sE  = g_sums[256 + cc], sE2 = g_sums[384 + cc];
            float sX  = g_sums[512 + cc];
            float sD  = sE - (float)NKN * sL;
            float sD2 = sE2 - 2.0f * sX + (float)NKN * sL2;
            mean = sD * invBNK;
            var  = sD2 * invBNK - mean * mean;
        }
        float a = gamma[c] * rsqrtf(var + 1e-5f);
        sa[c] = a;
        sb[c] = beta[c] - mean * a;
    }
    __syncthreads();

    const float4 a1 = *(const float4*)&sa[c4];
    const float4 b1 = *(const float4*)&sb[c4];
    const float4 a2 = *(const float4*)&sa[128 + c4];
    const float4 b2 = *(const float4*)&sb[128 + c4];

    for (int t = 0; t < 4; t++) {
        const int col = wrp * 4 + t;
        const int bn = bn0 + col;
        int my_idx = 0;
        if (lane < 16) my_idx = knn[bn * NKN + lane];
        const float4 l = *(const float4*)&g_Y[(size_t)bn * 256 + c4];
        const int boff = bn & ~(NN - 1);
        float4 S = {0,0,0,0};
#pragma unroll
        for (int k = 0; k < 16; k++) {
            const int m = __shfl_sync(0xffffffffu, my_idx, k);
            const float4 e = *(const float4*)&g_Y[((size_t)(boff + m)) * 256 + 128 + c4];
            S.x += fmaxf(fmaf(a2.x, e.x - l.x, b2.x), 0.0f);
            S.y += fmaxf(fmaf(a2.y, e.y - l.y, b2.y), 0.0f);
            S.z += fmaxf(fmaf(a2.z, e.z - l.z, b2.z), 0.0f);
            S.w += fmaxf(fmaf(a2.w, e.w - l.w, b2.w), 0.0f);
        }
        tile[col * 257 + c4 + 0] = fmaxf(fmaf(a1.x, l.x, b1.x), 0.0f);
        tile[col * 257 + c4 + 1] = fmaxf(fmaf(a1.y, l.y, b1.y), 0.0f);
        tile[col * 257 + c4 + 2] = fmaxf(fmaf(a1.z, l.z, b1.z), 0.0f);
        tile[col * 257 + c4 + 3] = fmaxf(fmaf(a1.w, l.w, b1.w), 0.0f);
        const float inv = 1.0f / 16.0f;
        tile[col * 257 + 128 + c4 + 0] = S.x * inv;
        tile[col * 257 + 128 + c4 + 1] = S.y * inv;
        tile[col * 257 + 128 + c4 + 2] = S.z * inv;
        tile[col * 257 + 128 + c4 + 3] = S.w * inv;
    }
    __syncthreads();

    const int b = bn0 >> 13;
    const int n0 = bn0 & (NN - 1);
#pragma unroll 4
    for (int i = 0; i < 32; i++) {
        int j = i * 256 + tid;
        int row = j >> 5, col = j & 31;
        out[((size_t)(b * 256 + row)) * NN + n0 + col] = tile[col * 257 + row];
    }
}

extern "C" void kernel_launch(void* const* d_in, const int* in_sizes, int n_in,
                              void* d_out, int out_size)
{
    const float* feat  = (const float*)d_in[0];
    const int*   knn   = (const int*)d_in[1];
    const float* W1    = (const float*)d_in[2];
    const float* W2    = (const float*)d_in[3];
    const float* gamma = (const float*)d_in[4];
    const float* beta  = (const float*)d_in[5];
    float* out = (float*)d_out;

    cudaFuncSetAttribute(mma_gemm_kernel,
                         cudaFuncAttributeMaxDynamicSharedMemorySize, SMEM_BYTES);

    mma_gemm_kernel<<<256, 512, SMEM_BYTES>>>(feat, W1, W2);
    stats_kernel<<<592, 256>>>(knn);
    output_kernel<<<1024, 256>>>(knn, gamma, beta, out);
}